// round 15
// baseline (speedup 1.0000x reference)
#include <cuda_runtime.h>
#include <cuda_fp16.h>
#include <cstdint>

#define Bdim  4
#define Sdim  1024
#define Hdim  1024
#define ENTn  16
#define INNER 64
#define NOUT  2048
#define NEGC  1.0e12f
#define WSCALE 256.0f
#define WINV   0.00390625f

// Scratch (allocation-free rule: __device__ globals)
__device__ __half g_Q[Bdim*ENTn*Sdim*INNER];   // [b][h][s][d] f16
__device__ __half g_K[Bdim*ENTn*Sdim*INNER];
__device__ uint8_t g_X8[Bdim*Sdim*Hdim];       // X in e4m3 [m][k]
__device__ uint8_t g_W8[NOUT*Hdim];            // (W*256)^T in e4m3 [n][k]
__device__ float g_sin[Sdim*(INNER/2)];        // [s][j]
__device__ float g_cos[Sdim*(INNER/2)];
__device__ int g_done[512];                    // per-gemm-CTA completion flags

__device__ __forceinline__ void cp16(void* s, const void* g){
    uint32_t sa = (uint32_t)__cvta_generic_to_shared(s);
    asm volatile("cp.async.cg.shared.global [%0], [%1], 16;" :: "r"(sa), "l"(g));
}
__device__ __forceinline__ void cp_commit(){ asm volatile("cp.async.commit_group;" ::: "memory"); }
template<int N> __device__ __forceinline__ void cp_wait(){
    asm volatile("cp.async.wait_group %0;" :: "n"(N) : "memory");
}
__device__ __forceinline__ void ldsm_x4(uint32_t* r, uint32_t addr){
    asm volatile("ldmatrix.sync.aligned.m8n8.x4.shared.b16 {%0,%1,%2,%3}, [%4];"
        : "=r"(r[0]), "=r"(r[1]), "=r"(r[2]), "=r"(r[3]) : "r"(addr));
}
// fp8 inputs, f16 accumulators (2 C regs) — halves acc registers
__device__ __forceinline__ void mma_fp8_f16(uint32_t* c, const uint32_t* a, const uint32_t* b){
    asm volatile("mma.sync.aligned.m16n8k32.row.col.f16.e4m3.e4m3.f16 "
        "{%0,%1}, {%2,%3,%4,%5}, {%6,%7}, {%0,%1};"
        : "+r"(c[0]), "+r"(c[1])
        : "r"(a[0]), "r"(a[1]), "r"(a[2]), "r"(a[3]), "r"(b[0]), "r"(b[1]));
}
// f16 inputs, f16 accumulators (attn)
__device__ __forceinline__ void mma_f16acc(uint32_t* c, const uint32_t* a, const uint32_t* b){
    asm volatile("mma.sync.aligned.m16n8k16.row.col.f16.f16.f16.f16 "
        "{%0,%1}, {%2,%3,%4,%5}, {%6,%7}, {%0,%1};"
        : "+r"(c[0]), "+r"(c[1])
        : "r"(a[0]), "r"(a[1]), "r"(a[2]), "r"(a[3]), "r"(b[0]), "r"(b[1]));
}
__device__ __forceinline__ uint16_t f2e4m3x2(float hi, float lo){
    uint16_t u;
    asm("cvt.rn.satfinite.e4m3x2.f32 %0, %1, %2;" : "=h"(u) : "f"(hi), "f"(lo));
    return u;
}
__device__ __forceinline__ void stg_cs_f2(float* p, float x, float y){
    asm volatile("st.global.cs.v2.f32 [%0], {%1,%2};" :: "l"(p), "f"(x), "f"(y) : "memory");
}
__device__ __forceinline__ void stg_cs_f4(float* p, float4 v){
    asm volatile("st.global.cs.v4.f32 [%0], {%1,%2,%3,%4};"
        :: "l"(p), "f"(v.x), "f"(v.y), "f"(v.z), "f"(v.w) : "memory");
}

// ---------------------------------------------------------------------------
// PREP (single launch): sincos table + flag reset + X->e4m3 + W^T*256->e4m3
//   bid [0,128):    sincos (+ flag reset in bid 0)
//   bid [128,640):  prep_x (grid-stride x2)
//   bid [640,2688): prep_w tiles
// ---------------------------------------------------------------------------
__global__ void __launch_bounds__(256) prep_kernel(
    const float* __restrict__ X, const float* __restrict__ W)
{
    const int bid = blockIdx.x, tid = threadIdx.x;
    if (bid < 128){
        if (bid == 0){ g_done[tid] = 0; g_done[tid + 256] = 0; }
        int idx = bid*256 + tid;              // 0..32767 = Sdim*32
        int s = idx >> 5, j = idx & 31;
        float freq = powf(10000.0f, -(float)j * 0.03125f);
        float ang  = (float)s * freq;
        g_sin[idx] = sinf(ang);
        g_cos[idx] = cosf(ang);
        return;
    }
    if (bid < 640){
        int n4 = Bdim*Sdim*Hdim/4;
        for (int i = (bid-128)*256 + tid; i < n4; i += 512*256){
            float4 v = reinterpret_cast<const float4*>(X)[i];
            uint32_t lo = f2e4m3x2(v.y, v.x);
            uint32_t hi = f2e4m3x2(v.w, v.z);
            reinterpret_cast<uint32_t*>(g_X8)[i] = lo | (hi << 16);
        }
        return;
    }
    {
        __shared__ float t[32][33];
        int f = bid - 640;                    // 0..2047 = 64 x 32 tiles
        const int n0 = (f & 63)*32, k0 = (f >> 6)*32;
        const int tx = tid & 31, ty = tid >> 5;   // 32 x 8
        #pragma unroll
        for (int i = ty; i < 32; i += 8)
            t[i][tx] = W[(size_t)(k0+i)*NOUT + n0 + tx];
        __syncthreads();
        #pragma unroll
        for (int i = ty; i < 32; i += 8){
            uint16_t u = f2e4m3x2(0.0f, t[tx][i] * WSCALE);
            g_W8[(size_t)(n0+i)*Hdim + k0 + tx] = (uint8_t)(u & 0xFF);
        }
    }
}

// ---------------------------------------------------------------------------
// MEGA kernel, 3 CTAs/SM (<=85 regs via launch_bounds(256,3)).
// Bid schedule (FIFO dispatch, gcd(148,3)=1 -> each SM gets 2 gemm + 1 streamer):
//   bid in [0,768):    bid%3<2 -> gemm idx 2*(bid/3)+bid%3 ; else fill idx bid/3
//   bid in [768,2304): fill idx 256+(bid-768)
//   bid in [2304,4608): attn idx bid-2304 (head-major)
// GEMM: fp8 e4m3 x e4m3, f16 acc (scaled x256), CTA 128x128, 8 warps 32x64.
//       Signals g_done[gemm_idx] (release) after Q/K stores visible.
// ATTN: waits (acquire) on its two producer gemm CTAs only, f16-acc HMMA.
// FILL: exact-constant strictly-lower tiles, streaming stores.
// ---------------------------------------------------------------------------
#define G1STRB 80
#define STAGE_B (128*G1STRB*2)
#define SMEM_MEGA 40960
#define QK2STR 72

__global__ void __launch_bounds__(256, 3) mega_kernel(
    const float* __restrict__ bias, const float* __restrict__ tok,
    float* __restrict__ out)
{
    const int bid = blockIdx.x;
    const int tid = threadIdx.x;
    extern __shared__ uint8_t smu[];
    const uint32_t sbase = (uint32_t)__cvta_generic_to_shared(smu);
    const int lane = tid & 31, warp = tid >> 5;
    const int g = lane >> 2, tg = lane & 3;
    const int l7 = lane & 7;

    // ---- role decode ----
    int gemm_idx = -1, fill_idx = -1, attn_idx = -1;
    if (bid < 768){
        int r = bid % 3, q = bid / 3;
        if (r < 2) gemm_idx = 2*q + r; else fill_idx = q;
    } else if (bid < 2304){
        fill_idx = 256 + (bid - 768);
    } else {
        attn_idx = bid - 2304;
    }

    if (gemm_idx >= 0){
        // ================= FP8 GEMM1 + RoPE (f16 acc) =================
        const int ntile = gemm_idx >> 5, mtile = gemm_idx & 31; // head-major
        const int wm = warp >> 1, wn = warp & 1;                // 4x2, 32x64
        const uint8_t* Xb = g_X8 + (size_t)mtile*128*Hdim;
        const uint8_t* Wb = g_W8 + (size_t)ntile*128*Hdim;

        const int selA_r  = ((lane >> 3) & 1) * 8;
        const int selA_cb = (lane >> 4) * 16;
        const int selB_r  = (lane >> 4) * 8;
        const int selB_cb = ((lane >> 3) & 1) * 16;

        uint32_t acc[2][8][2];
        #pragma unroll
        for (int a=0;a<2;a++)
            #pragma unroll
            for (int bq=0;bq<8;bq++){ acc[a][bq][0]=0u; acc[a][bq][1]=0u; }

        auto load_stage = [&](int ks, int b){
            uint8_t* Ad = smu + b*STAGE_B;
            uint8_t* Bd = Ad + 128*G1STRB;
            const uint8_t* xs = Xb + ks*64;
            const uint8_t* ws = Wb + ks*64;
            #pragma unroll
            for (int i=0;i<2;i++){
                int c = tid + i*256;
                int row = c >> 2, cb = (c & 3) << 4;
                cp16(Ad + row*G1STRB + cb, xs + (size_t)row*Hdim + cb);
                cp16(Bd + row*G1STRB + cb, ws + (size_t)row*Hdim + cb);
            }
            cp_commit();
        };

        load_stage(0, 0);
        int buf = 0;
        for (int ks = 0; ks < 16; ks++){
            if (ks < 15){ load_stage(ks+1, buf^1); cp_wait<1>(); }
            else        { cp_wait<0>(); }
            __syncthreads();
            const uint32_t abase = sbase + buf*STAGE_B;
            const uint32_t bbase = abase + 128*G1STRB;
            #pragma unroll
            for (int kk=0; kk<2; kk++){
                const int k0b = kk*32;
                uint32_t af[2][4], bf[8][2];
                #pragma unroll
                for (int mt=0; mt<2; mt++){
                    int row = wm*32 + mt*16 + selA_r + l7;
                    ldsm_x4(af[mt], abase + row*G1STRB + k0b + selA_cb);
                }
                #pragma unroll
                for (int ntp=0; ntp<4; ntp++){
                    int row = wn*64 + ntp*16 + selB_r + l7;
                    uint32_t q[4];
                    ldsm_x4(q, bbase + row*G1STRB + k0b + selB_cb);
                    bf[2*ntp  ][0] = q[0]; bf[2*ntp  ][1] = q[1];
                    bf[2*ntp+1][0] = q[2]; bf[2*ntp+1][1] = q[3];
                }
                #pragma unroll
                for (int mt=0; mt<2; mt++)
                    #pragma unroll
                    for (int nt=0; nt<8; nt++)
                        mma_fp8_f16(acc[mt][nt], af[mt], bf[nt]);
            }
            __syncthreads();
            buf ^= 1;
        }

        // Epilogue: un-scale (1/256) + bias + RoPE, f16 out
        #pragma unroll
        for (int nt=0; nt<8; nt++){
            const int n_loc = wn*64 + nt*8 + 2*tg;
            const int c = ntile*128 + n_loc;
            const int h = c >> 7, r = c & 127;
            const int d = r & 63, jj = d >> 1;
            __half* dst = (r < 64) ? g_Q : g_K;
            const float b0 = bias[c], b1 = bias[c+1];
            #pragma unroll
            for (int mt=0; mt<2; mt++){
                #pragma unroll
                for (int p=0; p<2; p++){
                    int m = mtile*128 + wm*32 + mt*16 + g + p*8;
                    int bb = m >> 10, s = m & 1023;
                    float sv = g_sin[s*32 + jj], cv = g_cos[s*32 + jj];
                    __half2 hv = *reinterpret_cast<__half2*>(&acc[mt][nt][p]);
                    float v0 = __half2float(hv.x) * WINV + b0;
                    float v1 = __half2float(hv.y) * WINV + b1;
                    __half2 o;
                    o.x = __float2half_rn(v0*cv - v1*sv);
                    o.y = __float2half_rn(v1*cv + v0*sv);
                    int idx = ((bb*ENTn + h)*Sdim + s)*INNER + d;
                    *reinterpret_cast<__half2*>(dst + idx) = o;
                }
            }
        }
        // Signal: this (head, mtile) slice of Q/K is globally visible.
        __threadfence();
        __syncthreads();
        if (tid == 0)
            asm volatile("st.release.gpu.global.s32 [%0], %1;"
                         :: "l"(&g_done[gemm_idx]), "r"(1) : "memory");
        return;
    }

    if (fill_idx >= 0){
        // ================= constant fill (strictly-lower tiles) =============
        int f = fill_idx;
        int z = f / 28, t = f % 28;
        int mt = 1; while (t >= mt){ t -= mt; mt++; }
        const int ntile = t;
        float* outb = out + ((size_t)z << 20);
        const float* padp = tok + (z >> 4)*Sdim + ntile*128;

        const int n4 = lane << 2;
        const int m0 = mt*128 + warp;
        float4 pv = *reinterpret_cast<const float4*>(padp + n4);
        float4 val;
        val.x = (-(1.0f - pv.x)*NEGC - NEGC)*0.125f;
        val.y = (-(1.0f - pv.y)*NEGC - NEGC)*0.125f;
        val.z = (-(1.0f - pv.z)*NEGC - NEGC)*0.125f;
        val.w = (-(1.0f - pv.w)*NEGC - NEGC)*0.125f;
        const int ncol = ntile*128 + n4;
        #pragma unroll
        for (int i = 0; i < 16; i++)
            stg_cs_f4(outb + ((size_t)(m0 + i*8) << 10) + ncol, val);
        return;
    }

    // ================= attn tile (upper/diagonal), f16 acc =================
    {
        int a = attn_idx;
        const int h = a / 144;              // head-major: matches gemm order
        int r2 = a % 144;
        const int bI = r2 / 36;
        int t = r2 % 36;
        int mtile = 0; while (t >= 8 - mtile){ t -= 8 - mtile; mtile++; }
        const int ntile = mtile + t;
        const int z = bI*ENTn + h;

        // Wait for the two producer gemm CTAs: (h, bI*8+mtile), (h, bI*8+ntile)
        if (tid == 0){
            const int f0 = h*32 + bI*8 + mtile;
            const int f1 = h*32 + bI*8 + ntile;
            int v;
            do { asm volatile("ld.acquire.gpu.global.s32 %0, [%1];"
                              : "=r"(v) : "l"(&g_done[f0]));
                 if (!v) __nanosleep(64);
            } while (!v);
            do { asm volatile("ld.acquire.gpu.global.s32 %0, [%1];"
                              : "=r"(v) : "l"(&g_done[f1]));
                 if (!v) __nanosleep(64);
            } while (!v);
        }
        __syncthreads();

        float* outb = out + ((size_t)z << 20);
        const float* padp = tok + bI*Sdim + ntile*128;
        __half* Qs = reinterpret_cast<__half*>(smu);
        __half* Ks = Qs + 128*QK2STR;
        __shared__ float pad_s[128];
        if (tid < 128) pad_s[tid] = padp[tid];

        const __half* Qg = g_Q + ((size_t)z*Sdim + (size_t)mtile*128)*INNER;
        const __half* Kg = g_K + ((size_t)z*Sdim + (size_t)ntile*128)*INNER;
        #pragma unroll
        for (int i=0;i<4;i++){
            int t2 = tid + i*256;
            int row = t2 >> 3, ch = (t2 & 7) << 3;
            cp16(Qs + row*QK2STR + ch, Qg + row*INNER + ch);
            cp16(Ks + row*QK2STR + ch, Kg + row*INNER + ch);
        }
        cp_commit();
        cp_wait<0>();
        __syncthreads();

        const int wm = warp >> 1, wn = warp & 1;
        const int selA_r = ((lane >> 3) & 1) * 8;
        const int selA_c = (lane >> 4) * 8;
        const int selB_r = (lane >> 4) * 8;
        const int selB_c = ((lane >> 3) & 1) * 8;
        const uint32_t qbase = sbase;
        const uint32_t kbase = sbase + (128*QK2STR)*2;

        uint32_t acc[2][8][2];
        #pragma unroll
        for (int aa=0;aa<2;aa++)
            #pragma unroll
            for (int bq=0;bq<8;bq++){ acc[aa][bq][0]=0u; acc[aa][bq][1]=0u; }

        #pragma unroll
        for (int kk=0; kk<4; kk++){
            const int k0 = kk*16;
            uint32_t af[2][4], bf[8][2];
            #pragma unroll
            for (int mt=0; mt<2; mt++){
                int row = wm*32 + mt*16 + selA_r + l7;
                ldsm_x4(af[mt], qbase + (row*QK2STR + k0 + selA_c)*2);
            }
            #pragma unroll
            for (int ntp=0; ntp<4; ntp++){
                int row = wn*64 + ntp*16 + selB_r + l7;
                uint32_t q[4];
                ldsm_x4(q, kbase + (row*QK2STR + k0 + selB_c)*2);
                bf[2*ntp  ][0] = q[0]; bf[2*ntp  ][1] = q[1];
                bf[2*ntp+1][0] = q[2]; bf[2*ntp+1][1] = q[3];
            }
            #pragma unroll
            for (int mt=0; mt<2; mt++)
                #pragma unroll
                for (int nt=0; nt<8; nt++)
                    mma_f16acc(acc[mt][nt], af[mt], bf[nt]);
        }

        #pragma unroll
        for (int mt=0; mt<2; mt++){
            #pragma unroll
            for (int nt=0; nt<8; nt++){
                const int n_loc = wn*64 + nt*8 + 2*tg;
                const int n = ntile*128 + n_loc;
                const float p0 = pad_s[n_loc], p1 = pad_s[n_loc+1];
                #pragma unroll
                for (int p=0; p<2; p++){
                    const int m = mtile*128 + wm*32 + mt*16 + g + p*8;
                    __half2 hv = *reinterpret_cast<__half2*>(&acc[mt][nt][p]);
                    float a0 = __half2float(hv.x), a1 = __half2float(hv.y);
                    float v0 = a0 * p0 - (1.0f - p0)*NEGC - ((n   < m) ? NEGC : 0.0f);
                    float v1 = a1 * p1 - (1.0f - p1)*NEGC - ((n+1 < m) ? NEGC : 0.0f);
                    stg_cs_f2(outb + ((size_t)m << 10) + n, v0*0.125f, v1*0.125f);
                }
            }
        }
    }
}

// ---------------------------------------------------------------------------
extern "C" void kernel_launch(void* const* d_in, const int* in_sizes, int n_in,
                              void* d_out, int out_size)
{
    const float* X    = (const float*)d_in[0];
    const float* W    = (const float*)d_in[1];
    const float* bias = (const float*)d_in[2];
    const float* tok  = (const float*)d_in[3];
    float* out = (float*)d_out;

    cudaFuncSetAttribute(mega_kernel,
        cudaFuncAttributeMaxDynamicSharedMemorySize, SMEM_MEGA);

    prep_kernel<<<2688, 256>>>(X, W);
    mega_kernel<<<4608, 256, SMEM_MEGA>>>(bias, tok, out);
}

// round 16
// speedup vs baseline: 1.0541x; 1.0541x over previous
#include <cuda_runtime.h>
#include <cuda_fp16.h>
#include <cstdint>

#define Bdim  4
#define Sdim  1024
#define Hdim  1024
#define ENTn  16
#define INNER 64
#define NOUT  2048
#define NEGC  1.0e12f
#define WSCALE 256.0f
#define WINV   0.00390625f

// Scratch (allocation-free rule: __device__ globals)
__device__ __half g_Q[Bdim*ENTn*Sdim*INNER];   // [b][h][s][d] f16
__device__ __half g_K[Bdim*ENTn*Sdim*INNER];
__device__ uint8_t g_X8[Bdim*Sdim*Hdim];       // X in e4m3 [m][k]
__device__ uint8_t g_W8[NOUT*Hdim];            // (W*256)^T in e4m3 [n][k]
__device__ float g_sin[Sdim*(INNER/2)];        // [s][j]
__device__ float g_cos[Sdim*(INNER/2)];
__device__ int g_done[512];                    // per-gemm-CTA completion flags

__device__ __forceinline__ void cp16(void* s, const void* g){
    uint32_t sa = (uint32_t)__cvta_generic_to_shared(s);
    asm volatile("cp.async.cg.shared.global [%0], [%1], 16;" :: "r"(sa), "l"(g));
}
__device__ __forceinline__ void cp_commit(){ asm volatile("cp.async.commit_group;" ::: "memory"); }
template<int N> __device__ __forceinline__ void cp_wait(){
    asm volatile("cp.async.wait_group %0;" :: "n"(N) : "memory");
}
__device__ __forceinline__ void ldsm_x4(uint32_t* r, uint32_t addr){
    asm volatile("ldmatrix.sync.aligned.m8n8.x4.shared.b16 {%0,%1,%2,%3}, [%4];"
        : "=r"(r[0]), "=r"(r[1]), "=r"(r[2]), "=r"(r[3]) : "r"(addr));
}
// fp8 inputs, f32 accumulators (R14-proven gemm path)
__device__ __forceinline__ void mma_fp8(float* c, const uint32_t* a, const uint32_t* b){
    asm volatile("mma.sync.aligned.m16n8k32.row.col.f32.e4m3.e4m3.f32 "
        "{%0,%1,%2,%3}, {%4,%5,%6,%7}, {%8,%9}, {%0,%1,%2,%3};"
        : "+f"(c[0]), "+f"(c[1]), "+f"(c[2]), "+f"(c[3])
        : "r"(a[0]), "r"(a[1]), "r"(a[2]), "r"(a[3]), "r"(b[0]), "r"(b[1]));
}
// f16 inputs, f32 accumulators (R14-proven attn path)
__device__ __forceinline__ void mma_f32acc(float* c, const uint32_t* a, const uint32_t* b){
    asm volatile("mma.sync.aligned.m16n8k16.row.col.f32.f16.f16.f32 "
        "{%0,%1,%2,%3}, {%4,%5,%6,%7}, {%8,%9}, {%0,%1,%2,%3};"
        : "+f"(c[0]), "+f"(c[1]), "+f"(c[2]), "+f"(c[3])
        : "r"(a[0]), "r"(a[1]), "r"(a[2]), "r"(a[3]), "r"(b[0]), "r"(b[1]));
}
__device__ __forceinline__ uint16_t f2e4m3x2(float hi, float lo){
    uint16_t u;
    asm("cvt.rn.satfinite.e4m3x2.f32 %0, %1, %2;" : "=h"(u) : "f"(hi), "f"(lo));
    return u;
}
__device__ __forceinline__ void stg_cs_f2(float* p, float x, float y){
    asm volatile("st.global.cs.v2.f32 [%0], {%1,%2};" :: "l"(p), "f"(x), "f"(y) : "memory");
}
__device__ __forceinline__ void stg_cs_f4(float* p, float4 v){
    asm volatile("st.global.cs.v4.f32 [%0], {%1,%2,%3,%4};"
        :: "l"(p), "f"(v.x), "f"(v.y), "f"(v.z), "f"(v.w) : "memory");
}

// ---------------------------------------------------------------------------
// PREP (single launch): sincos table + flag reset + X->e4m3 + W^T*256->e4m3
// ---------------------------------------------------------------------------
__global__ void __launch_bounds__(256) prep_kernel(
    const float* __restrict__ X, const float* __restrict__ W)
{
    const int bid = blockIdx.x, tid = threadIdx.x;
    if (bid < 128){
        if (bid == 0){ g_done[tid] = 0; g_done[tid + 256] = 0; }
        int idx = bid*256 + tid;              // 0..32767 = Sdim*32
        int s = idx >> 5, j = idx & 31;
        float freq = powf(10000.0f, -(float)j * 0.03125f);
        float ang  = (float)s * freq;
        g_sin[idx] = sinf(ang);
        g_cos[idx] = cosf(ang);
        return;
    }
    if (bid < 640){
        int n4 = Bdim*Sdim*Hdim/4;
        for (int i = (bid-128)*256 + tid; i < n4; i += 512*256){
            float4 v = reinterpret_cast<const float4*>(X)[i];
            uint32_t lo = f2e4m3x2(v.y, v.x);
            uint32_t hi = f2e4m3x2(v.w, v.z);
            reinterpret_cast<uint32_t*>(g_X8)[i] = lo | (hi << 16);
        }
        return;
    }
    {
        __shared__ float t[32][33];
        int f = bid - 640;                    // 0..2047 = 64 x 32 tiles
        const int n0 = (f & 63)*32, k0 = (f >> 6)*32;
        const int tx = tid & 31, ty = tid >> 5;   // 32 x 8
        #pragma unroll
        for (int i = ty; i < 32; i += 8)
            t[i][tx] = W[(size_t)(k0+i)*NOUT + n0 + tx];
        __syncthreads();
        #pragma unroll
        for (int i = ty; i < 32; i += 8){
            uint16_t u = f2e4m3x2(0.0f, t[tx][i] * WSCALE);
            g_W8[(size_t)(n0+i)*Hdim + k0 + tx] = (uint8_t)(u & 0xFF);
        }
    }
}

// ---------------------------------------------------------------------------
// MEGA kernel, 2 CTAs/SM (R14-proven occupancy; no streamer/gemm smem-port
// contention). Bid schedule:
//   bid in [0,512):    gemm, head-major (ntile=bid>>5, mtile=bid&31) ->
//                      heads complete in wave order. Signals g_done[bid].
//   bid in [512,4608): idx=bid-512; 16-bid groups: pos<9 -> attn (9*256=2304,
//                      head-major), else fill (7*256=1792). Interleaving keeps
//                      streaming slots fed with READY work during gemm wave 2.
// ATTN waits (acquire+nanosleep) only on its TWO producer gemm CTAs.
// Deadlock-free: all gemm bids precede all waiters; gemm never waits.
// ---------------------------------------------------------------------------
#define G1STRB 80
#define STAGE_B (128*G1STRB*2)
#define SMEM_MEGA 40960
#define QK2STR 72

__global__ void __launch_bounds__(256, 2) mega_kernel(
    const float* __restrict__ bias, const float* __restrict__ tok,
    float* __restrict__ out)
{
    const int bid = blockIdx.x;
    const int tid = threadIdx.x;
    extern __shared__ uint8_t smu[];
    const uint32_t sbase = (uint32_t)__cvta_generic_to_shared(smu);
    const int lane = tid & 31, warp = tid >> 5;
    const int g = lane >> 2, tg = lane & 3;
    const int l7 = lane & 7;

    // ---- role decode ----
    int gemm_idx = -1, fill_idx = -1, attn_idx = -1;
    if (bid < 512){
        gemm_idx = bid;
    } else {
        int idx = bid - 512;
        int grp = idx >> 4, pos = idx & 15;
        if (pos < 9) attn_idx = grp*9 + pos;
        else         fill_idx = grp*7 + (pos - 9);
    }

    if (gemm_idx >= 0){
        // ================= FP8 GEMM1 + RoPE (f32 acc, R14) =================
        const int ntile = gemm_idx >> 5, mtile = gemm_idx & 31; // head-major
        const int wm = warp >> 1, wn = warp & 1;                // 4x2, 32x64
        const uint8_t* Xb = g_X8 + (size_t)mtile*128*Hdim;
        const uint8_t* Wb = g_W8 + (size_t)ntile*128*Hdim;

        const int selA_r  = ((lane >> 3) & 1) * 8;
        const int selA_cb = (lane >> 4) * 16;
        const int selB_r  = (lane >> 4) * 8;
        const int selB_cb = ((lane >> 3) & 1) * 16;

        float acc[2][8][4];
        #pragma unroll
        for (int a=0;a<2;a++)
            #pragma unroll
            for (int bq=0;bq<8;bq++)
                #pragma unroll
                for (int k=0;k<4;k++) acc[a][bq][k]=0.f;

        auto load_stage = [&](int ks, int b){
            uint8_t* Ad = smu + b*STAGE_B;
            uint8_t* Bd = Ad + 128*G1STRB;
            const uint8_t* xs = Xb + ks*64;
            const uint8_t* ws = Wb + ks*64;
            #pragma unroll
            for (int i=0;i<2;i++){
                int c = tid + i*256;
                int row = c >> 2, cb = (c & 3) << 4;
                cp16(Ad + row*G1STRB + cb, xs + (size_t)row*Hdim + cb);
                cp16(Bd + row*G1STRB + cb, ws + (size_t)row*Hdim + cb);
            }
            cp_commit();
        };

        load_stage(0, 0);
        int buf = 0;
        for (int ks = 0; ks < 16; ks++){
            if (ks < 15){ load_stage(ks+1, buf^1); cp_wait<1>(); }
            else        { cp_wait<0>(); }
            __syncthreads();
            const uint32_t abase = sbase + buf*STAGE_B;
            const uint32_t bbase = abase + 128*G1STRB;
            #pragma unroll
            for (int kk=0; kk<2; kk++){
                const int k0b = kk*32;
                uint32_t af[2][4], bf[8][2];
                #pragma unroll
                for (int mt=0; mt<2; mt++){
                    int row = wm*32 + mt*16 + selA_r + l7;
                    ldsm_x4(af[mt], abase + row*G1STRB + k0b + selA_cb);
                }
                #pragma unroll
                for (int ntp=0; ntp<4; ntp++){
                    int row = wn*64 + ntp*16 + selB_r + l7;
                    uint32_t q[4];
                    ldsm_x4(q, bbase + row*G1STRB + k0b + selB_cb);
                    bf[2*ntp  ][0] = q[0]; bf[2*ntp  ][1] = q[1];
                    bf[2*ntp+1][0] = q[2]; bf[2*ntp+1][1] = q[3];
                }
                #pragma unroll
                for (int mt=0; mt<2; mt++)
                    #pragma unroll
                    for (int nt=0; nt<8; nt++)
                        mma_fp8(acc[mt][nt], af[mt], bf[nt]);
            }
            __syncthreads();
            buf ^= 1;
        }

        // Epilogue: un-scale (1/256) + bias + RoPE, f16 out
        #pragma unroll
        for (int nt=0; nt<8; nt++){
            const int n_loc = wn*64 + nt*8 + 2*tg;
            const int c = ntile*128 + n_loc;
            const int h = c >> 7, r = c & 127;
            const int d = r & 63, jj = d >> 1;
            __half* dst = (r < 64) ? g_Q : g_K;
            const float b0 = bias[c], b1 = bias[c+1];
            #pragma unroll
            for (int mt=0; mt<2; mt++){
                #pragma unroll
                for (int p=0; p<2; p++){
                    int m = mtile*128 + wm*32 + mt*16 + g + p*8;
                    int bb = m >> 10, s = m & 1023;
                    float sv = g_sin[s*32 + jj], cv = g_cos[s*32 + jj];
                    float v0 = acc[mt][nt][2*p]   * WINV + b0;
                    float v1 = acc[mt][nt][2*p+1] * WINV + b1;
                    __half2 o;
                    o.x = __float2half_rn(v0*cv - v1*sv);
                    o.y = __float2half_rn(v1*cv + v0*sv);
                    int idx = ((bb*ENTn + h)*Sdim + s)*INNER + d;
                    *reinterpret_cast<__half2*>(dst + idx) = o;
                }
            }
        }
        // Signal: this (head, mtile) slice of Q/K is globally visible.
        __threadfence();
        __syncthreads();
        if (tid == 0)
            asm volatile("st.release.gpu.global.s32 [%0], %1;"
                         :: "l"(&g_done[gemm_idx]), "r"(1) : "memory");
        return;
    }

    if (fill_idx >= 0){
        // ================= constant fill (strictly-lower tiles) =============
        int f = fill_idx;
        int z = f / 28, t = f % 28;
        int mt = 1; while (t >= mt){ t -= mt; mt++; }
        const int ntile = t;
        float* outb = out + ((size_t)z << 20);
        const float* padp = tok + (z >> 4)*Sdim + ntile*128;

        const int n4 = lane << 2;
        const int m0 = mt*128 + warp;
        float4 pv = *reinterpret_cast<const float4*>(padp + n4);
        float4 val;
        val.x = (-(1.0f - pv.x)*NEGC - NEGC)*0.125f;
        val.y = (-(1.0f - pv.y)*NEGC - NEGC)*0.125f;
        val.z = (-(1.0f - pv.z)*NEGC - NEGC)*0.125f;
        val.w = (-(1.0f - pv.w)*NEGC - NEGC)*0.125f;
        const int ncol = ntile*128 + n4;
        #pragma unroll
        for (int i = 0; i < 16; i++)
            stg_cs_f4(outb + ((size_t)(m0 + i*8) << 10) + ncol, val);
        return;
    }

    // ================= attn tile (upper/diagonal), f32 acc =================
    {
        int a = attn_idx;
        const int h = a / 144;              // head-major: matches gemm order
        int r2 = a % 144;
        const int bI = r2 / 36;
        int t = r2 % 36;
        int mtile = 0; while (t >= 8 - mtile){ t -= 8 - mtile; mtile++; }
        const int ntile = mtile + t;
        const int z = bI*ENTn + h;

        // Wait for the two producer gemm CTAs: (h, bI*8+mtile), (h, bI*8+ntile)
        if (tid == 0){
            const int f0 = h*32 + bI*8 + mtile;
            const int f1 = h*32 + bI*8 + ntile;
            int v;
            do { asm volatile("ld.acquire.gpu.global.s32 %0, [%1];"
                              : "=r"(v) : "l"(&g_done[f0]));
                 if (!v) __nanosleep(128);
            } while (!v);
            do { asm volatile("ld.acquire.gpu.global.s32 %0, [%1];"
                              : "=r"(v) : "l"(&g_done[f1]));
                 if (!v) __nanosleep(128);
            } while (!v);
        }
        __syncthreads();

        float* outb = out + ((size_t)z << 20);
        const float* padp = tok + bI*Sdim + ntile*128;
        __half* Qs = reinterpret_cast<__half*>(smu);
        __half* Ks = Qs + 128*QK2STR;
        __shared__ float pad_s[128];
        if (tid < 128) pad_s[tid] = padp[tid];

        const __half* Qg = g_Q + ((size_t)z*Sdim + (size_t)mtile*128)*INNER;
        const __half* Kg = g_K + ((size_t)z*Sdim + (size_t)ntile*128)*INNER;
        #pragma unroll
        for (int i=0;i<4;i++){
            int t2 = tid + i*256;
            int row = t2 >> 3, ch = (t2 & 7) << 3;
            cp16(Qs + row*QK2STR + ch, Qg + row*INNER + ch);
            cp16(Ks + row*QK2STR + ch, Kg + row*INNER + ch);
        }
        cp_commit();
        cp_wait<0>();
        __syncthreads();

        const int wm = warp >> 1, wn = warp & 1;
        const int selA_r = ((lane >> 3) & 1) * 8;
        const int selA_c = (lane >> 4) * 8;
        const int selB_r = (lane >> 4) * 8;
        const int selB_c = ((lane >> 3) & 1) * 8;
        const uint32_t qbase = sbase;
        const uint32_t kbase = sbase + (128*QK2STR)*2;

        float acc[2][8][4];
        #pragma unroll
        for (int aa=0;aa<2;aa++)
            #pragma unroll
            for (int bq=0;bq<8;bq++)
                #pragma unroll
                for (int k=0;k<4;k++) acc[aa][bq][k]=0.f;

        #pragma unroll
        for (int kk=0; kk<4; kk++){
            const int k0 = kk*16;
            uint32_t af[2][4], bf[8][2];
            #pragma unroll
            for (int mt=0; mt<2; mt++){
                int row = wm*32 + mt*16 + selA_r + l7;
                ldsm_x4(af[mt], qbase + (row*QK2STR + k0 + selA_c)*2);
            }
            #pragma unroll
            for (int ntp=0; ntp<4; ntp++){
                int row = wn*64 + ntp*16 + selB_r + l7;
                uint32_t q[4];
                ldsm_x4(q, kbase + (row*QK2STR + k0 + selB_c)*2);
                bf[2*ntp  ][0] = q[0]; bf[2*ntp  ][1] = q[1];
                bf[2*ntp+1][0] = q[2]; bf[2*ntp+1][1] = q[3];
            }
            #pragma unroll
            for (int mt=0; mt<2; mt++)
                #pragma unroll
                for (int nt=0; nt<8; nt++)
                    mma_f32acc(acc[mt][nt], af[mt], bf[nt]);
        }

        #pragma unroll
        for (int mt=0; mt<2; mt++){
            #pragma unroll
            for (int nt=0; nt<8; nt++){
                const int n_loc = wn*64 + nt*8 + 2*tg;
                const int n = ntile*128 + n_loc;
                const float p0 = pad_s[n_loc], p1 = pad_s[n_loc+1];
                #pragma unroll
                for (int p=0; p<2; p++){
                    const int m = mtile*128 + wm*32 + mt*16 + g + p*8;
                    float v0 = acc[mt][nt][2*p]   * p0 - (1.0f - p0)*NEGC - ((n   < m) ? NEGC : 0.0f);
                    float v1 = acc[mt][nt][2*p+1] * p1 - (1.0f - p1)*NEGC - ((n+1 < m) ? NEGC : 0.0f);
                    stg_cs_f2(outb + ((size_t)m << 10) + n, v0*0.125f, v1*0.125f);
                }
            }
        }
    }
}

// ---------------------------------------------------------------------------
extern "C" void kernel_launch(void* const* d_in, const int* in_sizes, int n_in,
                              void* d_out, int out_size)
{
    const float* X    = (const float*)d_in[0];
    const float* W    = (const float*)d_in[1];
    const float* bias = (const float*)d_in[2];
    const float* tok  = (const float*)d_in[3];
    float* out = (float*)d_out;

    cudaFuncSetAttribute(mega_kernel,
        cudaFuncAttributeMaxDynamicSharedMemorySize, SMEM_MEGA);

    prep_kernel<<<2688, 256>>>(X, W);
    mega_kernel<<<4608, 256, SMEM_MEGA>>>(bias, tok, out);
}